// round 15
// baseline (speedup 1.0000x reference)
#include <cuda_runtime.h>
#include <math.h>

// ---------------------------------------------------------------------------
// RUNG combined model, sparse formulation, round 5.
// N=4096, IN=512, H=256, OUT=64, PROP_STEP=4, nnz ~ 262k.
// vs R14 (434.7us):
// - edge_y: 8 lanes/edge, 4 edges in flight per warp (3-level butterfly
//   instead of 5-level serial warp reduce; SHFL lat=26cyc was the bottleneck).
// - GEMMs: 128-thr blocks, 8x4 micro-tile, double-buffered smem (1 sync/step).
// - quantile machinery unchanged (R14-proven): chunks/pick/refine/final.
// ---------------------------------------------------------------------------

#define MAXN   4096
#define MAXH   256
#define MAXOUT 64
#define MAXE   (1 << 22)

#define EPS_F     1e-8f
#define A_SCAD    3.7f
#define LAM_CONST (1.0f/0.9f - 1.0f)
#define FULLM     0xffffffffu

#define NCHUNK 64            // hist1 chunks (65536 / 1024)

// ------------------------- device scratch -------------------------
__device__ float    g_D[MAXN];
__device__ float    g_invDsq[MAXN];
__device__ int      g_cnt[MAXN];
__device__ int      g_rowptr[MAXN + 1];
__device__ int      g_nnz;
__device__ __align__(16) unsigned g_bits[MAXN * (MAXN / 32)];
__device__ int      g_col[MAXE];
__device__ float    g_y[MAXE];
__device__ __align__(16) float g_H1[MAXN * MAXH];
__device__ __align__(16) float g_F0[MAXN * MAXOUT];
__device__ __align__(16) float g_FcA[MAXN * MAXOUT];
__device__ __align__(16) float g_FcB[MAXN * MAXOUT];
__device__ __align__(16) float g_Fu[MAXN * MAXOUT];
__device__ unsigned g_hist1[65536];
__device__ unsigned g_chunk[NCHUNK];
__device__ unsigned short g_buf0[MAXE];
__device__ unsigned short g_buf1[MAXE];
__device__ int      g_c0, g_c1;
__device__ unsigned g_b0, g_b1;
__device__ int      g_rem0, g_rem1;
__device__ float    g_lamc;

// ------------------------- helpers -------------------------
__device__ __forceinline__ float scad_w(float y, float lam) {
    if (y <= lam) return 1.0f;
    float al = A_SCAD * lam;
    if (y <= al) return (al - y) / ((A_SCAD - 1.0f) * fmaxf(y, EPS_F));
    return 0.0f;
}
__device__ __forceinline__ float sigmoidf_(float x) { return 1.0f / (1.0f + expf(-x)); }

// ------------------------- K1: bitmask + degree (+zero hist1) ----------------
__global__ void k_rowstats(const float* __restrict__ A, int N) {
    int gid = blockIdx.x * blockDim.x + threadIdx.x;
    if (gid < 65536) g_hist1[gid] = 0u;      // grid is 512*256 = 131072 threads

    int lane = threadIdx.x & 31;
    int i = gid >> 5;
    if (i >= N) return;
    const float* row = A + (size_t)i * N;
    int nw = N >> 5;
    int c = 0;
    for (int w = 0; w < nw; w += 4) {
        int j0 = w * 32 + lane;
        float v0 = row[j0];
        float v1 = row[j0 + 32];
        float v2 = row[j0 + 64];
        float v3 = row[j0 + 96];
        unsigned m0 = __ballot_sync(FULLM, v0 > 0.0f && (j0      ) != i);
        unsigned m1 = __ballot_sync(FULLM, v1 > 0.0f && (j0 + 32 ) != i);
        unsigned m2 = __ballot_sync(FULLM, v2 > 0.0f && (j0 + 64 ) != i);
        unsigned m3 = __ballot_sync(FULLM, v3 > 0.0f && (j0 + 96 ) != i);
        if (lane == 0) {
            *(uint4*)&g_bits[(size_t)i * nw + w] = make_uint4(m0, m1, m2, m3);
            c += __popc(m0) + __popc(m1) + __popc(m2) + __popc(m3);
        }
    }
    if (lane == 0) {
        float D = (float)c + 1.0f;
        g_D[i] = D;
        g_invDsq[i] = rsqrtf(D);
        g_cnt[i] = c;
    }
}

// ------------------------- K2: exclusive scan -------------------------
__global__ void k_scan(int N) {
    __shared__ int sd[1024];
    int t = threadIdx.x;
    int running = 0;
    for (int base = 0; base < N; base += 1024) {
        int v = (base + t < N) ? g_cnt[base + t] : 0;
        sd[t] = v;
        __syncthreads();
        for (int off = 1; off < 1024; off <<= 1) {
            int x = (t >= off) ? sd[t - off] : 0;
            __syncthreads();
            sd[t] += x;
            __syncthreads();
        }
        if (base + t < N) g_rowptr[base + t] = running + sd[t] - v;
        running += sd[1023];
        __syncthreads();
    }
    if (t == 0) { g_rowptr[N] = running; g_nnz = running; }
}

// ------------------------- K3: CSR fill from bitmask -------------------------
__global__ void k_fill(int N) {
    int warp = (blockIdx.x * blockDim.x + threadIdx.x) >> 5;
    int lane = threadIdx.x & 31;
    if (warp >= N) return;
    int nw = N >> 5;
    int base = g_rowptr[warp];
    for (int w0 = 0; w0 < nw; w0 += 32) {
        unsigned word = (w0 + lane < nw) ? g_bits[(size_t)warp * nw + w0 + lane] : 0u;
        int pc = __popc(word);
        int inc = pc;
#pragma unroll
        for (int o = 1; o < 32; o <<= 1) {
            int x = __shfl_up_sync(FULLM, inc, o);
            if (lane >= o) inc += x;
        }
        int mybase = base + inc - pc;
        unsigned m = word;
        while (m) {
            int b = __ffs(m) - 1;
            m &= m - 1;
            g_col[mybase++] = (w0 + lane) * 32 + b;
        }
        base += __shfl_sync(FULLM, inc, 31);
    }
}

// ------------------------- GEMM1: 64x64 tile, 8x4 micro, 128 thr, dbuf -------
__global__ void k_gemm1(const float* __restrict__ A, const float* __restrict__ B,
                        const float* __restrict__ bias, float* __restrict__ C,
                        int M, int K, int N) {
    __shared__ __align__(16) float sA[2][16][64];
    __shared__ __align__(16) float sB[2][16][64];
    int tid = threadIdx.x;                 // 128
    int tx = tid & 15, ty = tid >> 4;      // ty 0..7
    int row0 = blockIdx.y * 64, col0 = blockIdx.x * 64;
    int mA = tid & 63, qA = tid >> 6;      // qA 0..1 (handles qA, qA+2)
    int nB4 = (tid & 15) * 4, kB = tid >> 4;  // kB 0..7 (handles kB, kB+8)
    float acc[8][4] = {};

    const float* Arow = A + (size_t)(row0 + mA) * K;
    float4 a0 = *(const float4*)(Arow + qA * 4);
    float4 a1 = *(const float4*)(Arow + (qA + 2) * 4);
    float4 b0 = *(const float4*)(B + (size_t)kB * N + col0 + nB4);
    float4 b1 = *(const float4*)(B + (size_t)(kB + 8) * N + col0 + nB4);

    sA[0][qA * 4 + 0][mA] = a0.x; sA[0][qA * 4 + 1][mA] = a0.y;
    sA[0][qA * 4 + 2][mA] = a0.z; sA[0][qA * 4 + 3][mA] = a0.w;
    sA[0][(qA + 2) * 4 + 0][mA] = a1.x; sA[0][(qA + 2) * 4 + 1][mA] = a1.y;
    sA[0][(qA + 2) * 4 + 2][mA] = a1.z; sA[0][(qA + 2) * 4 + 3][mA] = a1.w;
    *(float4*)&sB[0][kB][nB4] = b0;
    *(float4*)&sB[0][kB + 8][nB4] = b1;
    __syncthreads();

    int nsteps = K >> 4;
    int buf = 0;
    for (int s = 0; s < nsteps; s++) {
        if (s + 1 < nsteps) {
            int k0n = (s + 1) << 4;
            a0 = *(const float4*)(Arow + k0n + qA * 4);
            a1 = *(const float4*)(Arow + k0n + (qA + 2) * 4);
            b0 = *(const float4*)(B + (size_t)(k0n + kB) * N + col0 + nB4);
            b1 = *(const float4*)(B + (size_t)(k0n + kB + 8) * N + col0 + nB4);
        }
#pragma unroll
        for (int kk = 0; kk < 16; kk++) {
            float4 av0 = *(const float4*)&sA[buf][kk][ty * 8];
            float4 av1 = *(const float4*)&sA[buf][kk][ty * 8 + 4];
            float4 bv  = *(const float4*)&sB[buf][kk][tx * 4];
            float a_[8] = {av0.x, av0.y, av0.z, av0.w, av1.x, av1.y, av1.z, av1.w};
            float b_[4] = {bv.x, bv.y, bv.z, bv.w};
#pragma unroll
            for (int i = 0; i < 8; i++)
#pragma unroll
                for (int j = 0; j < 4; j++)
                    acc[i][j] = fmaf(a_[i], b_[j], acc[i][j]);
        }
        if (s + 1 < nsteps) {
            buf ^= 1;
            sA[buf][qA * 4 + 0][mA] = a0.x; sA[buf][qA * 4 + 1][mA] = a0.y;
            sA[buf][qA * 4 + 2][mA] = a0.z; sA[buf][qA * 4 + 3][mA] = a0.w;
            sA[buf][(qA + 2) * 4 + 0][mA] = a1.x; sA[buf][(qA + 2) * 4 + 1][mA] = a1.y;
            sA[buf][(qA + 2) * 4 + 2][mA] = a1.z; sA[buf][(qA + 2) * 4 + 3][mA] = a1.w;
            *(float4*)&sB[buf][kB][nB4] = b0;
            *(float4*)&sB[buf][kB + 8][nB4] = b1;
            __syncthreads();
        }
    }
    float4 bb = *(const float4*)(bias + col0 + tx * 4);
    float bl[4] = {bb.x, bb.y, bb.z, bb.w};
#pragma unroll
    for (int i = 0; i < 8; i++) {
        int r = row0 + ty * 8 + i;
        float4 v;
        v.x = fmaxf(acc[i][0] + bl[0], 0.0f);
        v.y = fmaxf(acc[i][1] + bl[1], 0.0f);
        v.z = fmaxf(acc[i][2] + bl[2], 0.0f);
        v.w = fmaxf(acc[i][3] + bl[3], 0.0f);
        *(float4*)(C + (size_t)r * N + col0 + tx * 4) = v;
    }
}

// ------------------------- GEMM2 + fused Fu epilogue (128 thr, dbuf) ---------
__global__ void k_gemm2fu(const float* __restrict__ B, const float* __restrict__ bias,
                          int M, int K, int N) {
    const float* __restrict__ A = g_H1;
    __shared__ __align__(16) float sA[2][16][64];
    __shared__ __align__(16) float sB[2][16][64];
    int tid = threadIdx.x;
    int tx = tid & 15, ty = tid >> 4;
    int row0 = blockIdx.y * 64;
    int mA = tid & 63, qA = tid >> 6;
    int nB4 = (tid & 15) * 4, kB = tid >> 4;
    float acc[8][4] = {};

    const float* Arow = A + (size_t)(row0 + mA) * K;
    float4 a0 = *(const float4*)(Arow + qA * 4);
    float4 a1 = *(const float4*)(Arow + (qA + 2) * 4);
    float4 b0 = *(const float4*)(B + (size_t)kB * N + nB4);
    float4 b1 = *(const float4*)(B + (size_t)(kB + 8) * N + nB4);

    sA[0][qA * 4 + 0][mA] = a0.x; sA[0][qA * 4 + 1][mA] = a0.y;
    sA[0][qA * 4 + 2][mA] = a0.z; sA[0][qA * 4 + 3][mA] = a0.w;
    sA[0][(qA + 2) * 4 + 0][mA] = a1.x; sA[0][(qA + 2) * 4 + 1][mA] = a1.y;
    sA[0][(qA + 2) * 4 + 2][mA] = a1.z; sA[0][(qA + 2) * 4 + 3][mA] = a1.w;
    *(float4*)&sB[0][kB][nB4] = b0;
    *(float4*)&sB[0][kB + 8][nB4] = b1;
    __syncthreads();

    int nsteps = K >> 4;
    int buf = 0;
    for (int s = 0; s < nsteps; s++) {
        if (s + 1 < nsteps) {
            int k0n = (s + 1) << 4;
            a0 = *(const float4*)(Arow + k0n + qA * 4);
            a1 = *(const float4*)(Arow + k0n + (qA + 2) * 4);
            b0 = *(const float4*)(B + (size_t)(k0n + kB) * N + nB4);
            b1 = *(const float4*)(B + (size_t)(k0n + kB + 8) * N + nB4);
        }
#pragma unroll
        for (int kk = 0; kk < 16; kk++) {
            float4 av0 = *(const float4*)&sA[buf][kk][ty * 8];
            float4 av1 = *(const float4*)&sA[buf][kk][ty * 8 + 4];
            float4 bv  = *(const float4*)&sB[buf][kk][tx * 4];
            float a_[8] = {av0.x, av0.y, av0.z, av0.w, av1.x, av1.y, av1.z, av1.w};
            float b_[4] = {bv.x, bv.y, bv.z, bv.w};
#pragma unroll
            for (int i = 0; i < 8; i++)
#pragma unroll
                for (int j = 0; j < 4; j++)
                    acc[i][j] = fmaf(a_[i], b_[j], acc[i][j]);
        }
        if (s + 1 < nsteps) {
            buf ^= 1;
            sA[buf][qA * 4 + 0][mA] = a0.x; sA[buf][qA * 4 + 1][mA] = a0.y;
            sA[buf][qA * 4 + 2][mA] = a0.z; sA[buf][qA * 4 + 3][mA] = a0.w;
            sA[buf][(qA + 2) * 4 + 0][mA] = a1.x; sA[buf][(qA + 2) * 4 + 1][mA] = a1.y;
            sA[buf][(qA + 2) * 4 + 2][mA] = a1.z; sA[buf][(qA + 2) * 4 + 3][mA] = a1.w;
            *(float4*)&sB[buf][kB][nB4] = b0;
            *(float4*)&sB[buf][kB + 8][nB4] = b1;
            __syncthreads();
        }
    }
    float4 bb = *(const float4*)(bias + tx * 4);
    float bl[4] = {bb.x, bb.y, bb.z, bb.w};
#pragma unroll
    for (int i = 0; i < 8; i++) {
        int r = row0 + ty * 8 + i;
        float vv[4];
#pragma unroll
        for (int j = 0; j < 4; j++) vv[j] = acc[i][j] + bl[j];
        float4 v; v.x = vv[0]; v.y = vv[1]; v.z = vv[2]; v.w = vv[3];
        *(float4*)(g_F0 + (size_t)r * N + tx * 4) = v;
        // fused Fu: 16 lanes (tx) hold this row's 64 cols; contiguous 16-lane group
        float iq = g_invDsq[r];
        float fn[4];
        float ss = 0.0f;
#pragma unroll
        for (int j = 0; j < 4; j++) { fn[j] = vv[j] * iq; ss += fn[j] * fn[j]; }
#pragma unroll
        for (int o = 1; o < 16; o <<= 1) ss += __shfl_xor_sync(FULLM, ss, o);
        float d = fmaxf(sqrtf(ss), EPS_F);
        float4 u; u.x = fn[0] / d; u.y = fn[1] / d; u.z = fn[2] / d; u.w = fn[3] / d;
        *(float4*)(g_Fu + (size_t)r * N + tx * 4) = u;
    }
}

// ------------------------- per-edge y: 8 lanes/edge, 4 edges in flight -------
__global__ void k_edge_y(int N) {
    int warp = (blockIdx.x * blockDim.x + threadIdx.x) >> 5;
    int lane = threadIdx.x & 31;
    if (warp >= N) return;
    int i = warp;
    int sub = lane >> 3;          // 0..3: which edge in the group of 4
    int sl  = lane & 7;           // 0..7: position within edge

    const float4* Fui = (const float4*)(g_Fu + (size_t)i * 64);
    float4 fa = Fui[sl * 2];
    float4 fb = Fui[sl * 2 + 1];

    int s = g_rowptr[i], e = g_rowptr[i + 1];
    for (int base = s; base < e; base += 4) {
        int p = base + sub;
        bool valid = (p < e);
        int j = valid ? g_col[p] : i;
        const float4* Fuj = (const float4*)(g_Fu + (size_t)j * 64);
        float4 ga = Fuj[sl * 2];
        float4 gb = Fuj[sl * 2 + 1];
        float d;
        d = fa.x * ga.x;
        d = fmaf(fa.y, ga.y, d);
        d = fmaf(fa.z, ga.z, d);
        d = fmaf(fa.w, ga.w, d);
        d = fmaf(fb.x, gb.x, d);
        d = fmaf(fb.y, gb.y, d);
        d = fmaf(fb.z, gb.z, d);
        d = fmaf(fb.w, gb.w, d);
        d += __shfl_xor_sync(FULLM, d, 1);
        d += __shfl_xor_sync(FULLM, d, 2);
        d += __shfl_xor_sync(FULLM, d, 4);
        unsigned key = 0x80000000u | lane;
        if (valid && sl == 0) {
            float y = fminf(fmaxf(1.0f - d, 0.0f), 2.0f);
            g_y[p] = y;
            key = __float_as_uint(y) >> 16;
        }
        unsigned grp = __match_any_sync(FULLM, key);
        if (!(key & 0x80000000u)) {
            int leader = __ffs(grp) - 1;
            if (lane == leader) atomicAdd(&g_hist1[key], (unsigned)__popc(grp));
        }
    }
}

// ------------------------- pass 1a: chunk sums (64 blocks) -------------------
__global__ void k_chunks() {
    __shared__ unsigned sred[8];
    int tid = threadIdx.x;      // 256
    int base = blockIdx.x * 1024;
    unsigned s = 0;
#pragma unroll
    for (int q = 0; q < 4; q++) s += g_hist1[base + q * 256 + tid];
#pragma unroll
    for (int o = 16; o; o >>= 1) s += __shfl_xor_sync(FULLM, s, o);
    if ((tid & 31) == 0) sred[tid >> 5] = s;
    __syncthreads();
    if (tid < 8) {
        unsigned v = sred[tid];
#pragma unroll
        for (int o = 4; o; o >>= 1) v += __shfl_xor_sync(0xffu, v, o);
        if (tid == 0) g_chunk[blockIdx.x] = v;
    }
}

// ------------------------- pass 1b: pick buckets (1 block, 256 thr) ----------
__global__ void k_pick() {
    __shared__ int sW0, sR0, sW1, sR1;
    int tid = threadIdx.x;
    int m = g_nnz;
    if (m <= 0) {
        if (tid == 0) { g_b0 = 0; g_b1 = 0; g_rem0 = 0; g_rem1 = 0; g_c0 = 0; g_c1 = 0; }
        return;
    }
    long p3 = 3L * (long)(m - 1);
    int k0 = (int)(p3 >> 2);
    int k1 = (k0 + 1 < m) ? k0 + 1 : m - 1;
    if (tid == 0) {
        unsigned run = 0;
        for (int q = 0; q < NCHUNK; q++) {
            unsigned c = g_chunk[q];
            if ((unsigned)k0 >= run && (unsigned)k0 < run + c) { sW0 = q; sR0 = (int)((unsigned)k0 - run); }
            if ((unsigned)k1 >= run && (unsigned)k1 < run + c) { sW1 = q; sR1 = (int)((unsigned)k1 - run); }
            run += c;
        }
        g_c0 = 0; g_c1 = 0;
    }
    __syncthreads();
    for (int sel = 0; sel < 2; sel++) {
        int w = sel ? sW1 : sW0;
        unsigned rank = (unsigned)(sel ? sR1 : sR0);
        __shared__ unsigned h[1024];
        int base = w * 1024;
#pragma unroll
        for (int q = 0; q < 4; q++) h[q * 256 + tid] = g_hist1[base + q * 256 + tid];
        __syncthreads();
        __shared__ unsigned tsum[256];
        unsigned v0 = h[tid * 4], v1 = h[tid * 4 + 1], v2 = h[tid * 4 + 2], v3 = h[tid * 4 + 3];
        unsigned loc = v0 + v1 + v2 + v3;
        tsum[tid] = loc;
        __syncthreads();
        for (int off = 1; off < 256; off <<= 1) {
            unsigned x = (tid >= off) ? tsum[tid - off] : 0u;
            __syncthreads();
            tsum[tid] += x;
            __syncthreads();
        }
        unsigned exc = tsum[tid] - loc;
        unsigned r0 = exc, r1 = exc + v0, r2 = r1 + v1, r3 = r2 + v2, r4 = r3 + v3;
        if (rank >= r0 && rank < r4) {
            int b; unsigned pr;
            if (rank < r1)      { b = 0; pr = r0; }
            else if (rank < r2) { b = 1; pr = r1; }
            else if (rank < r3) { b = 2; pr = r2; }
            else                { b = 3; pr = r3; }
            if (sel == 0) { g_b0 = (unsigned)(base + tid * 4 + b); g_rem0 = (int)(rank - pr); }
            else          { g_b1 = (unsigned)(base + tid * 4 + b); g_rem1 = (int)(rank - pr); }
        }
        __syncthreads();
    }
}

// ------------------------- pass 2: collect candidates (+zero hist1) ----------
__global__ void k_qrefine() {
    int m = g_nnz;
    unsigned b0 = g_b0, b1 = g_b1;
    bool same = (b1 == b0);
    int gid = blockIdx.x * blockDim.x + threadIdx.x;
    int stride = gridDim.x * blockDim.x;
    for (int z = gid; z < 65536; z += stride) g_hist1[z] = 0u;
    for (int e = gid; e < m; e += stride) {
        unsigned bits = __float_as_uint(g_y[e]);
        unsigned hi = bits >> 16;
        if (hi == b0) {
            int idx = atomicAdd(&g_c0, 1);
            g_buf0[idx] = (unsigned short)(bits & 0xFFFFu);
        } else if (!same && hi == b1) {
            int idx = atomicAdd(&g_c1, 1);
            g_buf1[idx] = (unsigned short)(bits & 0xFFFFu);
        }
    }
}

// ------------------------- smem 8/8 radix select within a bucket -------------
__device__ void select16(const unsigned short* __restrict__ buf, int cnt, int rank,
                         unsigned* out /* shared */) {
    __shared__ unsigned h[256];
    __shared__ int sHB, sRem;
    int tid = threadIdx.x;
    h[tid] = 0u;
    __syncthreads();
    for (int i = tid; i < cnt; i += 256) atomicAdd(&h[buf[i] >> 8], 1u);
    __syncthreads();
    unsigned v = h[tid];
    for (int off = 1; off < 256; off <<= 1) {
        unsigned x = (tid >= off) ? h[tid - off] : 0u;
        __syncthreads();
        h[tid] += x;
        __syncthreads();
    }
    unsigned inc = h[tid], exc = inc - v;
    if ((unsigned)rank >= exc && (unsigned)rank < inc) { sHB = tid; sRem = (int)((unsigned)rank - exc); }
    __syncthreads();
    int hb = sHB, rem = sRem;
    h[tid] = 0u;
    __syncthreads();
    for (int i = tid; i < cnt; i += 256) {
        unsigned b = buf[i];
        if ((int)(b >> 8) == hb) atomicAdd(&h[b & 0xFFu], 1u);
    }
    __syncthreads();
    v = h[tid];
    for (int off = 1; off < 256; off <<= 1) {
        unsigned x = (tid >= off) ? h[tid - off] : 0u;
        __syncthreads();
        h[tid] += x;
        __syncthreads();
    }
    inc = h[tid]; exc = inc - v;
    if ((unsigned)rem >= exc && (unsigned)rem < inc) *out = ((unsigned)hb << 8) | (unsigned)tid;
    __syncthreads();
}

// ------------------------- finalize: select + lamc (1 block) -----------------
__global__ void k_qfinal(const float* __restrict__ lg0p, const float* __restrict__ rdp,
                         const float* __restrict__ rabp, int kiter) {
    __shared__ unsigned sLow[2];
    int m = g_nnz;
    unsigned b0 = g_b0, b1 = g_b1;
    bool same = (b1 == b0);
    if (m > 0) {
        int c0 = g_c0, c1 = g_c1;
        select16(g_buf0, c0, g_rem0, &sLow[0]);
        if (same) select16(g_buf0, c0, g_rem1, &sLow[1]);
        else      select16(g_buf1, c1, g_rem1, &sLow[1]);
    }
    if (threadIdx.x == 0) {
        float gd;
        if (m > 0) {
            float v0 = __uint_as_float((b0 << 16) | sLow[0]);
            float v1 = __uint_as_float((b1 << 16) | sLow[1]);
            long p3 = 3L * (long)(m - 1);
            float frac = (float)(p3 & 3) * 0.25f;
            gd = v0 + (v1 - v0) * frac;
        } else {
            gd = 1.0f;
        }
        gd = fmaxf(gd, EPS_F);
        float alpha = sigmoidf_(*rabp);
        float r = sigmoidf_(*rdp);
        float gp = expf(*lg0p);
        for (int q = 0; q < kiter; q++) gp *= r;
        g_lamc = alpha * (gp / A_SCAD) + (1.0f - alpha) * (gd / A_SCAD);
    }
}

// ------------------------- SpMM + Q_hat + update (+fused Fu) -----------------
__global__ void k_spmm(int src, int dst, float* __restrict__ dout, int N, int OUT,
                       int writeFu) {
    int i = blockIdx.x;
    int t = threadIdx.x;   // 64
    const float* __restrict__ Fc = (src == 0) ? g_F0 : (src == 1) ? g_FcA : g_FcB;
    float* __restrict__ Fout = (dst == 1) ? g_FcA : (dst == 2) ? g_FcB : dout;
    __shared__ float s_wsc[64];
    __shared__ int   s_col[64];
    __shared__ float s_q[2];
    __shared__ float s_n[2];
    float lamc = g_lamc;
    int s = g_rowptr[i], e = g_rowptr[i + 1];
    float acc = 0.0f, qpart = 0.0f;
    for (int base = s; base < e; base += 64) {
        int p = base + t;
        float wc = 0.0f; int col = 0;
        if (p < e) {
            float y = g_y[p];
            float wgt = scad_w(y, lamc);
            col = g_col[p];
            wc = wgt * g_invDsq[col];
            qpart += wgt;
        }
        s_wsc[t] = wc; s_col[t] = col;
        __syncthreads();
        int len = e - base; if (len > 64) len = 64;
        if (t < OUT) {
#pragma unroll 4
            for (int q = 0; q < len; q++)
                acc = fmaf(s_wsc[q], Fc[(size_t)s_col[q] * OUT + t], acc);
        }
        __syncthreads();
    }
#pragma unroll
    for (int o = 16; o; o >>= 1) qpart += __shfl_xor_sync(FULLM, qpart, o);
    if ((t & 31) == 0) s_q[t >> 5] = qpart;
    __syncthreads();
    float val = 0.0f;
    float iq = g_invDsq[i];
    if (t < OUT) {
        float Qh = (s_q[0] + s_q[1]) / g_D[i] + LAM_CONST;
        val = (acc * iq + LAM_CONST * g_F0[(size_t)i * OUT + t]) / Qh;
        Fout[(size_t)i * OUT + t] = val;
    }
    if (writeFu) {
        float fn = (t < OUT) ? val * iq : 0.0f;
        float ss = fn * fn;
#pragma unroll
        for (int o = 16; o; o >>= 1) ss += __shfl_xor_sync(FULLM, ss, o);
        if ((t & 31) == 0) s_n[t >> 5] = ss;
        __syncthreads();
        float nrm = sqrtf(s_n[0] + s_n[1]);
        float d = fmaxf(nrm, EPS_F);
        if (t < OUT) g_Fu[(size_t)i * OUT + t] = fn / d;
    }
}

// ------------------------- launch -------------------------
extern "C" void kernel_launch(void* const* d_in, const int* in_sizes, int n_in,
                              void* d_out, int out_size) {
    const float* A   = (const float*)d_in[0];
    const float* X   = (const float*)d_in[1];
    const float* W1  = (const float*)d_in[2];
    const float* b1  = (const float*)d_in[3];
    const float* W2  = (const float*)d_in[4];
    const float* b2  = (const float*)d_in[5];
    const float* lg0 = (const float*)d_in[6];
    const float* rd  = (const float*)d_in[7];
    const float* rab = (const float*)d_in[8];
    float* out = (float*)d_out;

    int H   = in_sizes[3];
    int OUT = in_sizes[5];
    int IN  = in_sizes[2] / H;
    int N   = in_sizes[1] / IN;

    int warpBlocks = (N * 32 + 255) / 256;

    // graph structure (rowstats zeroes hist1 for iter 0)
    k_rowstats<<<warpBlocks, 256>>>(A, N);
    k_scan<<<1, 1024>>>(N);
    k_fill<<<warpBlocks, 256>>>(N);

    // MLP: F0 = relu(X@W1 + b1) @ W2 + b2 ; gemm2 fuses Fu epilogue
    float* H1p;  cudaGetSymbolAddress((void**)&H1p, g_H1);
    dim3 g1(H / 64, N / 64);
    k_gemm1<<<g1, 128>>>(X, W1, b1, H1p, N, IN, H);
    dim3 g2(1, N / 64);
    k_gemm2fu<<<g2, 128>>>(W2, b2, N, H, OUT);

    // propagation: F0 -> FcA -> FcB -> FcA -> d_out
    const int srcs[4] = {0, 1, 2, 1};
    const int dsts[4] = {1, 2, 1, 3};
    for (int k = 0; k < 4; k++) {
        k_edge_y<<<warpBlocks, 256>>>(N);
        k_chunks<<<NCHUNK, 256>>>();
        k_pick<<<1, 256>>>();
        k_qrefine<<<296, 256>>>();
        k_qfinal<<<1, 256>>>(lg0, rd, rab, k);
        k_spmm<<<N, 64>>>(srcs[k], dsts[k], out, N, OUT, (k < 3) ? 1 : 0);
    }
}

// round 16
// speedup vs baseline: 1.3604x; 1.3604x over previous
#include <cuda_runtime.h>
#include <math.h>

// ---------------------------------------------------------------------------
// RUNG combined model, sparse formulation, round 6.
// Base: R14 (434.7us, proven). Single change: k_edge_y uses 16 lanes/edge,
// 2 edges in flight, float4 loads, 4-level butterfly — but keeps R14's
// per-32-edge match_any aggregation cadence exactly (R15 showed per-4-edge
// flushing costs ~120us).
// ---------------------------------------------------------------------------

#define MAXN   4096
#define MAXH   256
#define MAXOUT 64
#define MAXE   (1 << 22)

#define EPS_F     1e-8f
#define A_SCAD    3.7f
#define LAM_CONST (1.0f/0.9f - 1.0f)
#define FULLM     0xffffffffu

#define NCHUNK 64            // hist1 chunks (65536 / 1024)

// ------------------------- device scratch -------------------------
__device__ float    g_D[MAXN];
__device__ float    g_invDsq[MAXN];
__device__ int      g_cnt[MAXN];
__device__ int      g_rowptr[MAXN + 1];
__device__ int      g_nnz;
__device__ __align__(16) unsigned g_bits[MAXN * (MAXN / 32)];
__device__ int      g_col[MAXE];
__device__ float    g_y[MAXE];
__device__ __align__(16) float g_H1[MAXN * MAXH];
__device__ __align__(16) float g_F0[MAXN * MAXOUT];
__device__ __align__(16) float g_FcA[MAXN * MAXOUT];
__device__ __align__(16) float g_FcB[MAXN * MAXOUT];
__device__ __align__(16) float g_Fu[MAXN * MAXOUT];
__device__ unsigned g_hist1[65536];
__device__ unsigned g_chunk[NCHUNK];
__device__ unsigned short g_buf0[MAXE];
__device__ unsigned short g_buf1[MAXE];
__device__ int      g_c0, g_c1;
__device__ unsigned g_b0, g_b1;
__device__ int      g_rem0, g_rem1;
__device__ float    g_lamc;

// ------------------------- helpers -------------------------
__device__ __forceinline__ float scad_w(float y, float lam) {
    if (y <= lam) return 1.0f;
    float al = A_SCAD * lam;
    if (y <= al) return (al - y) / ((A_SCAD - 1.0f) * fmaxf(y, EPS_F));
    return 0.0f;
}
__device__ __forceinline__ float sigmoidf_(float x) { return 1.0f / (1.0f + expf(-x)); }

// ------------------------- K1: bitmask + degree (+zero hist1) ----------------
__global__ void k_rowstats(const float* __restrict__ A, int N) {
    int gid = blockIdx.x * blockDim.x + threadIdx.x;
    if (gid < 65536) g_hist1[gid] = 0u;      // grid is 512*256 = 131072 threads

    int lane = threadIdx.x & 31;
    int i = gid >> 5;
    if (i >= N) return;
    const float* row = A + (size_t)i * N;
    int nw = N >> 5;
    int c = 0;
    for (int w = 0; w < nw; w += 4) {
        int j0 = w * 32 + lane;
        float v0 = row[j0];
        float v1 = row[j0 + 32];
        float v2 = row[j0 + 64];
        float v3 = row[j0 + 96];
        unsigned m0 = __ballot_sync(FULLM, v0 > 0.0f && (j0      ) != i);
        unsigned m1 = __ballot_sync(FULLM, v1 > 0.0f && (j0 + 32 ) != i);
        unsigned m2 = __ballot_sync(FULLM, v2 > 0.0f && (j0 + 64 ) != i);
        unsigned m3 = __ballot_sync(FULLM, v3 > 0.0f && (j0 + 96 ) != i);
        if (lane == 0) {
            *(uint4*)&g_bits[(size_t)i * nw + w] = make_uint4(m0, m1, m2, m3);
            c += __popc(m0) + __popc(m1) + __popc(m2) + __popc(m3);
        }
    }
    if (lane == 0) {
        float D = (float)c + 1.0f;
        g_D[i] = D;
        g_invDsq[i] = rsqrtf(D);
        g_cnt[i] = c;
    }
}

// ------------------------- K2: exclusive scan -------------------------
__global__ void k_scan(int N) {
    __shared__ int sd[1024];
    int t = threadIdx.x;
    int running = 0;
    for (int base = 0; base < N; base += 1024) {
        int v = (base + t < N) ? g_cnt[base + t] : 0;
        sd[t] = v;
        __syncthreads();
        for (int off = 1; off < 1024; off <<= 1) {
            int x = (t >= off) ? sd[t - off] : 0;
            __syncthreads();
            sd[t] += x;
            __syncthreads();
        }
        if (base + t < N) g_rowptr[base + t] = running + sd[t] - v;
        running += sd[1023];
        __syncthreads();
    }
    if (t == 0) { g_rowptr[N] = running; g_nnz = running; }
}

// ------------------------- K3: CSR fill from bitmask -------------------------
__global__ void k_fill(int N) {
    int warp = (blockIdx.x * blockDim.x + threadIdx.x) >> 5;
    int lane = threadIdx.x & 31;
    if (warp >= N) return;
    int nw = N >> 5;
    int base = g_rowptr[warp];
    for (int w0 = 0; w0 < nw; w0 += 32) {
        unsigned word = (w0 + lane < nw) ? g_bits[(size_t)warp * nw + w0 + lane] : 0u;
        int pc = __popc(word);
        int inc = pc;
#pragma unroll
        for (int o = 1; o < 32; o <<= 1) {
            int x = __shfl_up_sync(FULLM, inc, o);
            if (lane >= o) inc += x;
        }
        int mybase = base + inc - pc;
        unsigned m = word;
        while (m) {
            int b = __ffs(m) - 1;
            m &= m - 1;
            g_col[mybase++] = (w0 + lane) * 32 + b;
        }
        base += __shfl_sync(FULLM, inc, 31);
    }
}

// ------------------------- GEMM1: 64x64 tile, 4x4 micro, 256 thr (R14) -------
__global__ void k_gemm1(const float* __restrict__ A, const float* __restrict__ B,
                        const float* __restrict__ bias, float* __restrict__ C,
                        int M, int K, int N) {
    __shared__ __align__(16) float sA[16][64];
    __shared__ __align__(16) float sB[16][64];
    int tid = threadIdx.x;
    int tx = tid & 15, ty = tid >> 4;
    int row0 = blockIdx.y * 64, col0 = blockIdx.x * 64;
    int mA = tid & 63, qA = tid >> 6;
    int nB = (tid & 15) * 4, kB = tid >> 4;
    float acc[4][4] = {};

    float4 a4 = *(const float4*)(A + (size_t)(row0 + mA) * K + qA * 4);
    float4 b4 = *(const float4*)(B + (size_t)kB * N + col0 + nB);

    for (int k0 = 0; k0 < K; k0 += 16) {
        sA[qA * 4 + 0][mA] = a4.x; sA[qA * 4 + 1][mA] = a4.y;
        sA[qA * 4 + 2][mA] = a4.z; sA[qA * 4 + 3][mA] = a4.w;
        *(float4*)&sB[kB][nB] = b4;
        __syncthreads();
        if (k0 + 16 < K) {
            a4 = *(const float4*)(A + (size_t)(row0 + mA) * K + k0 + 16 + qA * 4);
            b4 = *(const float4*)(B + (size_t)(k0 + 16 + kB) * N + col0 + nB);
        }
#pragma unroll
        for (int kk = 0; kk < 16; kk++) {
            float4 av = *(const float4*)&sA[kk][ty * 4];
            float4 bv = *(const float4*)&sB[kk][tx * 4];
            float a_[4] = {av.x, av.y, av.z, av.w};
            float b_[4] = {bv.x, bv.y, bv.z, bv.w};
#pragma unroll
            for (int i = 0; i < 4; i++)
#pragma unroll
                for (int j = 0; j < 4; j++)
                    acc[i][j] = fmaf(a_[i], b_[j], acc[i][j]);
        }
        __syncthreads();
    }
    float4 bb = *(const float4*)(bias + col0 + tx * 4);
    float bl[4] = {bb.x, bb.y, bb.z, bb.w};
#pragma unroll
    for (int i = 0; i < 4; i++) {
        int r = row0 + ty * 4 + i;
        float4 v;
        v.x = fmaxf(acc[i][0] + bl[0], 0.0f);
        v.y = fmaxf(acc[i][1] + bl[1], 0.0f);
        v.z = fmaxf(acc[i][2] + bl[2], 0.0f);
        v.w = fmaxf(acc[i][3] + bl[3], 0.0f);
        *(float4*)(C + (size_t)r * N + col0 + tx * 4) = v;
    }
}

// ------------------------- GEMM2 + fused Fu epilogue (R14) -------------------
__global__ void k_gemm2fu(const float* __restrict__ B, const float* __restrict__ bias,
                          int M, int K, int N) {
    const float* __restrict__ A = g_H1;
    __shared__ __align__(16) float sA[16][64];
    __shared__ __align__(16) float sB[16][64];
    int tid = threadIdx.x;
    int tx = tid & 15, ty = tid >> 4;
    int row0 = blockIdx.y * 64;
    int mA = tid & 63, qA = tid >> 6;
    int nB = (tid & 15) * 4, kB = tid >> 4;
    float acc[4][4] = {};

    float4 a4 = *(const float4*)(A + (size_t)(row0 + mA) * K + qA * 4);
    float4 b4 = *(const float4*)(B + (size_t)kB * N + nB);

    for (int k0 = 0; k0 < K; k0 += 16) {
        sA[qA * 4 + 0][mA] = a4.x; sA[qA * 4 + 1][mA] = a4.y;
        sA[qA * 4 + 2][mA] = a4.z; sA[qA * 4 + 3][mA] = a4.w;
        *(float4*)&sB[kB][nB] = b4;
        __syncthreads();
        if (k0 + 16 < K) {
            a4 = *(const float4*)(A + (size_t)(row0 + mA) * K + k0 + 16 + qA * 4);
            b4 = *(const float4*)(B + (size_t)(k0 + 16 + kB) * N + nB);
        }
#pragma unroll
        for (int kk = 0; kk < 16; kk++) {
            float4 av = *(const float4*)&sA[kk][ty * 4];
            float4 bv = *(const float4*)&sB[kk][tx * 4];
            float a_[4] = {av.x, av.y, av.z, av.w};
            float b_[4] = {bv.x, bv.y, bv.z, bv.w};
#pragma unroll
            for (int i = 0; i < 4; i++)
#pragma unroll
                for (int j = 0; j < 4; j++)
                    acc[i][j] = fmaf(a_[i], b_[j], acc[i][j]);
        }
        __syncthreads();
    }
    float4 bb = *(const float4*)(bias + tx * 4);
    float bl[4] = {bb.x, bb.y, bb.z, bb.w};
#pragma unroll
    for (int i = 0; i < 4; i++) {
        int r = row0 + ty * 4 + i;
        float vv[4];
#pragma unroll
        for (int j = 0; j < 4; j++) vv[j] = acc[i][j] + bl[j];
        float4 v; v.x = vv[0]; v.y = vv[1]; v.z = vv[2]; v.w = vv[3];
        *(float4*)(g_F0 + (size_t)r * N + tx * 4) = v;
        float iq = g_invDsq[r];
        float fn[4];
        float ss = 0.0f;
#pragma unroll
        for (int j = 0; j < 4; j++) { fn[j] = vv[j] * iq; ss += fn[j] * fn[j]; }
#pragma unroll
        for (int o = 1; o < 16; o <<= 1) ss += __shfl_xor_sync(FULLM, ss, o);
        float d = fmaxf(sqrtf(ss), EPS_F);
        float4 u; u.x = fn[0] / d; u.y = fn[1] / d; u.z = fn[2] / d; u.w = fn[3] / d;
        *(float4*)(g_Fu + (size_t)r * N + tx * 4) = u;
    }
}

// ------------------------- per-edge y: 16 lanes/edge, 2 in flight ------------
// R14 aggregation cadence preserved: one __match_any_sync per 32 buffered keys.
__global__ void k_edge_y(int N) {
    int warp = (blockIdx.x * blockDim.x + threadIdx.x) >> 5;
    int lane = threadIdx.x & 31;
    if (warp >= N) return;
    int i = warp;
    int sub = lane >> 4;          // 0,1: which edge in the pair
    int sl  = lane & 15;          // position within edge

    float4 fa = ((const float4*)(g_Fu + (size_t)i * 64))[sl];

    int s = g_rowptr[i], e = g_rowptr[i + 1];
    unsigned myKey = 0x80000000u | lane;
    int cnt = 0;
    for (int base = s; base < e; base += 2) {
        int p = base + sub;
        bool valid = (p < e);
        int j = valid ? g_col[p] : i;
        float4 ga = ((const float4*)(g_Fu + (size_t)j * 64))[sl];
        float d;
        d = fa.x * ga.x;
        d = fmaf(fa.y, ga.y, d);
        d = fmaf(fa.z, ga.z, d);
        d = fmaf(fa.w, ga.w, d);
        d += __shfl_xor_sync(FULLM, d, 1);
        d += __shfl_xor_sync(FULLM, d, 2);
        d += __shfl_xor_sync(FULLM, d, 4);
        d += __shfl_xor_sync(FULLM, d, 8);
        float y = fminf(fmaxf(1.0f - d, 0.0f), 2.0f);
        if (valid && sl == 0) g_y[p] = y;          // lanes 0 and 16 store
        float y0 = __shfl_sync(FULLM, y, 0);
        float y1 = __shfl_sync(FULLM, y, 16);
        int nv = (e - base >= 2) ? 2 : 1;
        if (lane == cnt)                 myKey = __float_as_uint(y0) >> 16;
        if (lane == cnt + 1 && nv == 2)  myKey = __float_as_uint(y1) >> 16;
        cnt += nv;
        if (cnt == 32) {
            unsigned grp = __match_any_sync(FULLM, myKey);
            if (!(myKey & 0x80000000u)) {
                int leader = __ffs(grp) - 1;
                if (lane == leader) atomicAdd(&g_hist1[myKey], (unsigned)__popc(grp));
            }
            myKey = 0x80000000u | lane;
            cnt = 0;
        }
    }
    if (cnt) {
        unsigned grp = __match_any_sync(FULLM, myKey);
        if (!(myKey & 0x80000000u)) {
            int leader = __ffs(grp) - 1;
            if (lane == leader) atomicAdd(&g_hist1[myKey], (unsigned)__popc(grp));
        }
    }
}

// ------------------------- pass 1a: chunk sums (64 blocks) -------------------
__global__ void k_chunks() {
    __shared__ unsigned sred[8];
    int tid = threadIdx.x;      // 256
    int base = blockIdx.x * 1024;
    unsigned s = 0;
#pragma unroll
    for (int q = 0; q < 4; q++) s += g_hist1[base + q * 256 + tid];
#pragma unroll
    for (int o = 16; o; o >>= 1) s += __shfl_xor_sync(FULLM, s, o);
    if ((tid & 31) == 0) sred[tid >> 5] = s;
    __syncthreads();
    if (tid < 8) {
        unsigned v = sred[tid];
#pragma unroll
        for (int o = 4; o; o >>= 1) v += __shfl_xor_sync(0xffu, v, o);
        if (tid == 0) g_chunk[blockIdx.x] = v;
    }
}

// ------------------------- pass 1b: pick buckets (1 block, 256 thr) ----------
__global__ void k_pick() {
    __shared__ int sW0, sR0, sW1, sR1;
    int tid = threadIdx.x;
    int m = g_nnz;
    if (m <= 0) {
        if (tid == 0) { g_b0 = 0; g_b1 = 0; g_rem0 = 0; g_rem1 = 0; g_c0 = 0; g_c1 = 0; }
        return;
    }
    long p3 = 3L * (long)(m - 1);
    int k0 = (int)(p3 >> 2);
    int k1 = (k0 + 1 < m) ? k0 + 1 : m - 1;
    if (tid == 0) {
        unsigned run = 0;
        for (int q = 0; q < NCHUNK; q++) {
            unsigned c = g_chunk[q];
            if ((unsigned)k0 >= run && (unsigned)k0 < run + c) { sW0 = q; sR0 = (int)((unsigned)k0 - run); }
            if ((unsigned)k1 >= run && (unsigned)k1 < run + c) { sW1 = q; sR1 = (int)((unsigned)k1 - run); }
            run += c;
        }
        g_c0 = 0; g_c1 = 0;
    }
    __syncthreads();
    for (int sel = 0; sel < 2; sel++) {
        int w = sel ? sW1 : sW0;
        unsigned rank = (unsigned)(sel ? sR1 : sR0);
        __shared__ unsigned h[1024];
        int base = w * 1024;
#pragma unroll
        for (int q = 0; q < 4; q++) h[q * 256 + tid] = g_hist1[base + q * 256 + tid];
        __syncthreads();
        __shared__ unsigned tsum[256];
        unsigned v0 = h[tid * 4], v1 = h[tid * 4 + 1], v2 = h[tid * 4 + 2], v3 = h[tid * 4 + 3];
        unsigned loc = v0 + v1 + v2 + v3;
        tsum[tid] = loc;
        __syncthreads();
        for (int off = 1; off < 256; off <<= 1) {
            unsigned x = (tid >= off) ? tsum[tid - off] : 0u;
            __syncthreads();
            tsum[tid] += x;
            __syncthreads();
        }
        unsigned exc = tsum[tid] - loc;
        unsigned r0 = exc, r1 = exc + v0, r2 = r1 + v1, r3 = r2 + v2, r4 = r3 + v3;
        if (rank >= r0 && rank < r4) {
            int b; unsigned pr;
            if (rank < r1)      { b = 0; pr = r0; }
            else if (rank < r2) { b = 1; pr = r1; }
            else if (rank < r3) { b = 2; pr = r2; }
            else                { b = 3; pr = r3; }
            if (sel == 0) { g_b0 = (unsigned)(base + tid * 4 + b); g_rem0 = (int)(rank - pr); }
            else          { g_b1 = (unsigned)(base + tid * 4 + b); g_rem1 = (int)(rank - pr); }
        }
        __syncthreads();
    }
}

// ------------------------- pass 2: collect candidates (+zero hist1) ----------
__global__ void k_qrefine() {
    int m = g_nnz;
    unsigned b0 = g_b0, b1 = g_b1;
    bool same = (b1 == b0);
    int gid = blockIdx.x * blockDim.x + threadIdx.x;
    int stride = gridDim.x * blockDim.x;
    for (int z = gid; z < 65536; z += stride) g_hist1[z] = 0u;
    for (int e = gid; e < m; e += stride) {
        unsigned bits = __float_as_uint(g_y[e]);
        unsigned hi = bits >> 16;
        if (hi == b0) {
            int idx = atomicAdd(&g_c0, 1);
            g_buf0[idx] = (unsigned short)(bits & 0xFFFFu);
        } else if (!same && hi == b1) {
            int idx = atomicAdd(&g_c1, 1);
            g_buf1[idx] = (unsigned short)(bits & 0xFFFFu);
        }
    }
}

// ------------------------- smem 8/8 radix select within a bucket -------------
__device__ void select16(const unsigned short* __restrict__ buf, int cnt, int rank,
                         unsigned* out /* shared */) {
    __shared__ unsigned h[256];
    __shared__ int sHB, sRem;
    int tid = threadIdx.x;
    h[tid] = 0u;
    __syncthreads();
    for (int i = tid; i < cnt; i += 256) atomicAdd(&h[buf[i] >> 8], 1u);
    __syncthreads();
    unsigned v = h[tid];
    for (int off = 1; off < 256; off <<= 1) {
        unsigned x = (tid >= off) ? h[tid - off] : 0u;
        __syncthreads();
        h[tid] += x;
        __syncthreads();
    }
    unsigned inc = h[tid], exc = inc - v;
    if ((unsigned)rank >= exc && (unsigned)rank < inc) { sHB = tid; sRem = (int)((unsigned)rank - exc); }
    __syncthreads();
    int hb = sHB, rem = sRem;
    h[tid] = 0u;
    __syncthreads();
    for (int i = tid; i < cnt; i += 256) {
        unsigned b = buf[i];
        if ((int)(b >> 8) == hb) atomicAdd(&h[b & 0xFFu], 1u);
    }
    __syncthreads();
    v = h[tid];
    for (int off = 1; off < 256; off <<= 1) {
        unsigned x = (tid >= off) ? h[tid - off] : 0u;
        __syncthreads();
        h[tid] += x;
        __syncthreads();
    }
    inc = h[tid]; exc = inc - v;
    if ((unsigned)rem >= exc && (unsigned)rem < inc) *out = ((unsigned)hb << 8) | (unsigned)tid;
    __syncthreads();
}

// ------------------------- finalize: select + lamc (1 block) -----------------
__global__ void k_qfinal(const float* __restrict__ lg0p, const float* __restrict__ rdp,
                         const float* __restrict__ rabp, int kiter) {
    __shared__ unsigned sLow[2];
    int m = g_nnz;
    unsigned b0 = g_b0, b1 = g_b1;
    bool same = (b1 == b0);
    if (m > 0) {
        int c0 = g_c0, c1 = g_c1;
        select16(g_buf0, c0, g_rem0, &sLow[0]);
        if (same) select16(g_buf0, c0, g_rem1, &sLow[1]);
        else      select16(g_buf1, c1, g_rem1, &sLow[1]);
    }
    if (threadIdx.x == 0) {
        float gd;
        if (m > 0) {
            float v0 = __uint_as_float((b0 << 16) | sLow[0]);
            float v1 = __uint_as_float((b1 << 16) | sLow[1]);
            long p3 = 3L * (long)(m - 1);
            float frac = (float)(p3 & 3) * 0.25f;
            gd = v0 + (v1 - v0) * frac;
        } else {
            gd = 1.0f;
        }
        gd = fmaxf(gd, EPS_F);
        float alpha = sigmoidf_(*rabp);
        float r = sigmoidf_(*rdp);
        float gp = expf(*lg0p);
        for (int q = 0; q < kiter; q++) gp *= r;
        g_lamc = alpha * (gp / A_SCAD) + (1.0f - alpha) * (gd / A_SCAD);
    }
}

// ------------------------- SpMM + Q_hat + update (+fused Fu) -----------------
__global__ void k_spmm(int src, int dst, float* __restrict__ dout, int N, int OUT,
                       int writeFu) {
    int i = blockIdx.x;
    int t = threadIdx.x;   // 64
    const float* __restrict__ Fc = (src == 0) ? g_F0 : (src == 1) ? g_FcA : g_FcB;
    float* __restrict__ Fout = (dst == 1) ? g_FcA : (dst == 2) ? g_FcB : dout;
    __shared__ float s_wsc[64];
    __shared__ int   s_col[64];
    __shared__ float s_q[2];
    __shared__ float s_n[2];
    float lamc = g_lamc;
    int s = g_rowptr[i], e = g_rowptr[i + 1];
    float acc = 0.0f, qpart = 0.0f;
    for (int base = s; base < e; base += 64) {
        int p = base + t;
        float wc = 0.0f; int col = 0;
        if (p < e) {
            float y = g_y[p];
            float wgt = scad_w(y, lamc);
            col = g_col[p];
            wc = wgt * g_invDsq[col];
            qpart += wgt;
        }
        s_wsc[t] = wc; s_col[t] = col;
        __syncthreads();
        int len = e - base; if (len > 64) len = 64;
        if (t < OUT) {
#pragma unroll 4
            for (int q = 0; q < len; q++)
                acc = fmaf(s_wsc[q], Fc[(size_t)s_col[q] * OUT + t], acc);
        }
        __syncthreads();
    }
#pragma unroll
    for (int o = 16; o; o >>= 1) qpart += __shfl_xor_sync(FULLM, qpart, o);
    if ((t & 31) == 0) s_q[t >> 5] = qpart;
    __syncthreads();
    float val = 0.0f;
    float iq = g_invDsq[i];
    if (t < OUT) {
        float Qh = (s_q[0] + s_q[1]) / g_D[i] + LAM_CONST;
        val = (acc * iq + LAM_CONST * g_F0[(size_t)i * OUT + t]) / Qh;
        Fout[(size_t)i * OUT + t] = val;
    }
    if (writeFu) {
        float fn = (t < OUT) ? val * iq : 0.0f;
        float ss = fn * fn;
#pragma unroll
        for (int o = 16; o; o >>= 1) ss += __shfl_xor_sync(FULLM, ss, o);
        if ((t & 31) == 0) s_n[t >> 5] = ss;
        __syncthreads();
        float nrm = sqrtf(s_n[0] + s_n[1]);
        float d = fmaxf(nrm, EPS_F);
        if (t < OUT) g_Fu[(size_t)i * OUT + t] = fn / d;
    }
}

// ------------------------- launch -------------------------
extern "C" void kernel_launch(void* const* d_in, const int* in_sizes, int n_in,
                              void* d_out, int out_size) {
    const float* A   = (const float*)d_in[0];
    const float* X   = (const float*)d_in[1];
    const float* W1  = (const float*)d_in[2];
    const float* b1  = (const float*)d_in[3];
    const float* W2  = (const float*)d_in[4];
    const float* b2  = (const float*)d_in[5];
    const float* lg0 = (const float*)d_in[6];
    const float* rd  = (const float*)d_in[7];
    const float* rab = (const float*)d_in[8];
    float* out = (float*)d_out;

    int H   = in_sizes[3];
    int OUT = in_sizes[5];
    int IN  = in_sizes[2] / H;
    int N   = in_sizes[1] / IN;

    int warpBlocks = (N * 32 + 255) / 256;

    // graph structure (rowstats zeroes hist1 for iter 0)
    k_rowstats<<<warpBlocks, 256>>>(A, N);
    k_scan<<<1, 1024>>>(N);
    k_fill<<<warpBlocks, 256>>>(N);

    // MLP: F0 = relu(X@W1 + b1) @ W2 + b2 ; gemm2 fuses Fu epilogue
    float* H1p;  cudaGetSymbolAddress((void**)&H1p, g_H1);
    dim3 g1(H / 64, N / 64);
    k_gemm1<<<g1, 256>>>(X, W1, b1, H1p, N, IN, H);
    dim3 g2(1, N / 64);
    k_gemm2fu<<<g2, 256>>>(W2, b2, N, H, OUT);

    // propagation: F0 -> FcA -> FcB -> FcA -> d_out
    const int srcs[4] = {0, 1, 2, 1};
    const int dsts[4] = {1, 2, 1, 3};
    for (int k = 0; k < 4; k++) {
        k_edge_y<<<warpBlocks, 256>>>(N);
        k_chunks<<<NCHUNK, 256>>>();
        k_pick<<<1, 256>>>();
        k_qrefine<<<296, 256>>>();
        k_qfinal<<<1, 256>>>(lg0, rd, rab, k);
        k_spmm<<<N, 64>>>(srcs[k], dsts[k], out, N, OUT, (k < 3) ? 1 : 0);
    }
}

// round 17
// speedup vs baseline: 1.6741x; 1.2306x over previous
#include <cuda_runtime.h>
#include <math.h>

// ---------------------------------------------------------------------------
// RUNG combined model, sparse formulation, round 7.
// Base: R16 (408.4us, proven). Single change: exploit y symmetry.
// y_ij == y_ji exactly (same dot, same FP order), so edge_y computes only
// col > row edges (contiguous tail of each sorted row), scatters y to both
// (p, tr[p]), and histogram leaders add 2*popc. tr[] built once at setup
// by warp-per-row binary search. Everything else identical to R16.
// ---------------------------------------------------------------------------

#define MAXN   4096
#define MAXH   256
#define MAXOUT 64
#define MAXE   (1 << 22)

#define EPS_F     1e-8f
#define A_SCAD    3.7f
#define LAM_CONST (1.0f/0.9f - 1.0f)
#define FULLM     0xffffffffu

#define NCHUNK 64            // hist1 chunks (65536 / 1024)

// ------------------------- device scratch -------------------------
__device__ float    g_D[MAXN];
__device__ float    g_invDsq[MAXN];
__device__ int      g_cnt[MAXN];
__device__ int      g_rowptr[MAXN + 1];
__device__ int      g_nnz;
__device__ __align__(16) unsigned g_bits[MAXN * (MAXN / 32)];
__device__ int      g_col[MAXE];
__device__ int      g_tr[MAXE];
__device__ float    g_y[MAXE];
__device__ __align__(16) float g_H1[MAXN * MAXH];
__device__ __align__(16) float g_F0[MAXN * MAXOUT];
__device__ __align__(16) float g_FcA[MAXN * MAXOUT];
__device__ __align__(16) float g_FcB[MAXN * MAXOUT];
__device__ __align__(16) float g_Fu[MAXN * MAXOUT];
__device__ unsigned g_hist1[65536];
__device__ unsigned g_chunk[NCHUNK];
__device__ unsigned short g_buf0[MAXE];
__device__ unsigned short g_buf1[MAXE];
__device__ int      g_c0, g_c1;
__device__ unsigned g_b0, g_b1;
__device__ int      g_rem0, g_rem1;
__device__ float    g_lamc;

// ------------------------- helpers -------------------------
__device__ __forceinline__ float scad_w(float y, float lam) {
    if (y <= lam) return 1.0f;
    float al = A_SCAD * lam;
    if (y <= al) return (al - y) / ((A_SCAD - 1.0f) * fmaxf(y, EPS_F));
    return 0.0f;
}
__device__ __forceinline__ float sigmoidf_(float x) { return 1.0f / (1.0f + expf(-x)); }

// ------------------------- K1: bitmask + degree (+zero hist1) ----------------
__global__ void k_rowstats(const float* __restrict__ A, int N) {
    int gid = blockIdx.x * blockDim.x + threadIdx.x;
    if (gid < 65536) g_hist1[gid] = 0u;      // grid is 512*256 = 131072 threads

    int lane = threadIdx.x & 31;
    int i = gid >> 5;
    if (i >= N) return;
    const float* row = A + (size_t)i * N;
    int nw = N >> 5;
    int c = 0;
    for (int w = 0; w < nw; w += 4) {
        int j0 = w * 32 + lane;
        float v0 = row[j0];
        float v1 = row[j0 + 32];
        float v2 = row[j0 + 64];
        float v3 = row[j0 + 96];
        unsigned m0 = __ballot_sync(FULLM, v0 > 0.0f && (j0      ) != i);
        unsigned m1 = __ballot_sync(FULLM, v1 > 0.0f && (j0 + 32 ) != i);
        unsigned m2 = __ballot_sync(FULLM, v2 > 0.0f && (j0 + 64 ) != i);
        unsigned m3 = __ballot_sync(FULLM, v3 > 0.0f && (j0 + 96 ) != i);
        if (lane == 0) {
            *(uint4*)&g_bits[(size_t)i * nw + w] = make_uint4(m0, m1, m2, m3);
            c += __popc(m0) + __popc(m1) + __popc(m2) + __popc(m3);
        }
    }
    if (lane == 0) {
        float D = (float)c + 1.0f;
        g_D[i] = D;
        g_invDsq[i] = rsqrtf(D);
        g_cnt[i] = c;
    }
}

// ------------------------- K2: exclusive scan -------------------------
__global__ void k_scan(int N) {
    __shared__ int sd[1024];
    int t = threadIdx.x;
    int running = 0;
    for (int base = 0; base < N; base += 1024) {
        int v = (base + t < N) ? g_cnt[base + t] : 0;
        sd[t] = v;
        __syncthreads();
        for (int off = 1; off < 1024; off <<= 1) {
            int x = (t >= off) ? sd[t - off] : 0;
            __syncthreads();
            sd[t] += x;
            __syncthreads();
        }
        if (base + t < N) g_rowptr[base + t] = running + sd[t] - v;
        running += sd[1023];
        __syncthreads();
    }
    if (t == 0) { g_rowptr[N] = running; g_nnz = running; }
}

// ------------------------- K3: CSR fill from bitmask -------------------------
__global__ void k_fill(int N) {
    int warp = (blockIdx.x * blockDim.x + threadIdx.x) >> 5;
    int lane = threadIdx.x & 31;
    if (warp >= N) return;
    int nw = N >> 5;
    int base = g_rowptr[warp];
    for (int w0 = 0; w0 < nw; w0 += 32) {
        unsigned word = (w0 + lane < nw) ? g_bits[(size_t)warp * nw + w0 + lane] : 0u;
        int pc = __popc(word);
        int inc = pc;
#pragma unroll
        for (int o = 1; o < 32; o <<= 1) {
            int x = __shfl_up_sync(FULLM, inc, o);
            if (lane >= o) inc += x;
        }
        int mybase = base + inc - pc;
        unsigned m = word;
        while (m) {
            int b = __ffs(m) - 1;
            m &= m - 1;
            g_col[mybase++] = (w0 + lane) * 32 + b;
        }
        base += __shfl_sync(FULLM, inc, 31);
    }
}

// ------------------------- K4: transpose permutation -------------------------
// tr[p] = index q such that (col[q]==row(p)) within row col[p].
__global__ void k_transpose(int N) {
    int warp = (blockIdx.x * blockDim.x + threadIdx.x) >> 5;
    int lane = threadIdx.x & 31;
    if (warp >= N) return;
    int i = warp;
    int s = g_rowptr[i], e = g_rowptr[i + 1];
    for (int p = s + lane; p < e; p += 32) {
        int j = g_col[p];
        int lo = g_rowptr[j], hi = g_rowptr[j + 1];
        while (lo < hi) {
            int mid = (lo + hi) >> 1;
            if (g_col[mid] < i) lo = mid + 1; else hi = mid;
        }
        g_tr[p] = lo;   // g_col[lo] == i (guaranteed: graph is symmetric)
    }
}

// ------------------------- GEMM1: 64x64 tile, 4x4 micro, 256 thr (R14) -------
__global__ void k_gemm1(const float* __restrict__ A, const float* __restrict__ B,
                        const float* __restrict__ bias, float* __restrict__ C,
                        int M, int K, int N) {
    __shared__ __align__(16) float sA[16][64];
    __shared__ __align__(16) float sB[16][64];
    int tid = threadIdx.x;
    int tx = tid & 15, ty = tid >> 4;
    int row0 = blockIdx.y * 64, col0 = blockIdx.x * 64;
    int mA = tid & 63, qA = tid >> 6;
    int nB = (tid & 15) * 4, kB = tid >> 4;
    float acc[4][4] = {};

    float4 a4 = *(const float4*)(A + (size_t)(row0 + mA) * K + qA * 4);
    float4 b4 = *(const float4*)(B + (size_t)kB * N + col0 + nB);

    for (int k0 = 0; k0 < K; k0 += 16) {
        sA[qA * 4 + 0][mA] = a4.x; sA[qA * 4 + 1][mA] = a4.y;
        sA[qA * 4 + 2][mA] = a4.z; sA[qA * 4 + 3][mA] = a4.w;
        *(float4*)&sB[kB][nB] = b4;
        __syncthreads();
        if (k0 + 16 < K) {
            a4 = *(const float4*)(A + (size_t)(row0 + mA) * K + k0 + 16 + qA * 4);
            b4 = *(const float4*)(B + (size_t)(k0 + 16 + kB) * N + col0 + nB);
        }
#pragma unroll
        for (int kk = 0; kk < 16; kk++) {
            float4 av = *(const float4*)&sA[kk][ty * 4];
            float4 bv = *(const float4*)&sB[kk][tx * 4];
            float a_[4] = {av.x, av.y, av.z, av.w};
            float b_[4] = {bv.x, bv.y, bv.z, bv.w};
#pragma unroll
            for (int i = 0; i < 4; i++)
#pragma unroll
                for (int j = 0; j < 4; j++)
                    acc[i][j] = fmaf(a_[i], b_[j], acc[i][j]);
        }
        __syncthreads();
    }
    float4 bb = *(const float4*)(bias + col0 + tx * 4);
    float bl[4] = {bb.x, bb.y, bb.z, bb.w};
#pragma unroll
    for (int i = 0; i < 4; i++) {
        int r = row0 + ty * 4 + i;
        float4 v;
        v.x = fmaxf(acc[i][0] + bl[0], 0.0f);
        v.y = fmaxf(acc[i][1] + bl[1], 0.0f);
        v.z = fmaxf(acc[i][2] + bl[2], 0.0f);
        v.w = fmaxf(acc[i][3] + bl[3], 0.0f);
        *(float4*)(C + (size_t)r * N + col0 + tx * 4) = v;
    }
}

// ------------------------- GEMM2 + fused Fu epilogue (R14) -------------------
__global__ void k_gemm2fu(const float* __restrict__ B, const float* __restrict__ bias,
                          int M, int K, int N) {
    const float* __restrict__ A = g_H1;
    __shared__ __align__(16) float sA[16][64];
    __shared__ __align__(16) float sB[16][64];
    int tid = threadIdx.x;
    int tx = tid & 15, ty = tid >> 4;
    int row0 = blockIdx.y * 64;
    int mA = tid & 63, qA = tid >> 6;
    int nB = (tid & 15) * 4, kB = tid >> 4;
    float acc[4][4] = {};

    float4 a4 = *(const float4*)(A + (size_t)(row0 + mA) * K + qA * 4);
    float4 b4 = *(const float4*)(B + (size_t)kB * N + nB);

    for (int k0 = 0; k0 < K; k0 += 16) {
        sA[qA * 4 + 0][mA] = a4.x; sA[qA * 4 + 1][mA] = a4.y;
        sA[qA * 4 + 2][mA] = a4.z; sA[qA * 4 + 3][mA] = a4.w;
        *(float4*)&sB[kB][nB] = b4;
        __syncthreads();
        if (k0 + 16 < K) {
            a4 = *(const float4*)(A + (size_t)(row0 + mA) * K + k0 + 16 + qA * 4);
            b4 = *(const float4*)(B + (size_t)(k0 + 16 + kB) * N + nB);
        }
#pragma unroll
        for (int kk = 0; kk < 16; kk++) {
            float4 av = *(const float4*)&sA[kk][ty * 4];
            float4 bv = *(const float4*)&sB[kk][tx * 4];
            float a_[4] = {av.x, av.y, av.z, av.w};
            float b_[4] = {bv.x, bv.y, bv.z, bv.w};
#pragma unroll
            for (int i = 0; i < 4; i++)
#pragma unroll
                for (int j = 0; j < 4; j++)
                    acc[i][j] = fmaf(a_[i], b_[j], acc[i][j]);
        }
        __syncthreads();
    }
    float4 bb = *(const float4*)(bias + tx * 4);
    float bl[4] = {bb.x, bb.y, bb.z, bb.w};
#pragma unroll
    for (int i = 0; i < 4; i++) {
        int r = row0 + ty * 4 + i;
        float vv[4];
#pragma unroll
        for (int j = 0; j < 4; j++) vv[j] = acc[i][j] + bl[j];
        float4 v; v.x = vv[0]; v.y = vv[1]; v.z = vv[2]; v.w = vv[3];
        *(float4*)(g_F0 + (size_t)r * N + tx * 4) = v;
        float iq = g_invDsq[r];
        float fn[4];
        float ss = 0.0f;
#pragma unroll
        for (int j = 0; j < 4; j++) { fn[j] = vv[j] * iq; ss += fn[j] * fn[j]; }
#pragma unroll
        for (int o = 1; o < 16; o <<= 1) ss += __shfl_xor_sync(FULLM, ss, o);
        float d = fmaxf(sqrtf(ss), EPS_F);
        float4 u; u.x = fn[0] / d; u.y = fn[1] / d; u.z = fn[2] / d; u.w = fn[3] / d;
        *(float4*)(g_Fu + (size_t)r * N + tx * 4) = u;
    }
}

// ------------------------- per-edge y: symmetric (col > row only) ------------
// 16 lanes/edge, 2 in flight; y scattered to (p, tr[p]); hist adds 2/edge.
__global__ void k_edge_y(int N) {
    int warp = (blockIdx.x * blockDim.x + threadIdx.x) >> 5;
    int lane = threadIdx.x & 31;
    if (warp >= N) return;
    int i = warp;
    int sub = lane >> 4;          // 0,1: which edge in the pair
    int sl  = lane & 15;          // position within edge

    float4 fa = ((const float4*)(g_Fu + (size_t)i * 64))[sl];

    int s = g_rowptr[i], e = g_rowptr[i + 1];

    // find first edge with col > i (cols ascending) via ballot scan
    int start = e;
    for (int b = s; b < e; b += 32) {
        int p = b + lane;
        int c = (p < e) ? g_col[p] : 0x7fffffff;
        unsigned ball = __ballot_sync(FULLM, c > i);
        if (ball) { start = b + __ffs(ball) - 1; break; }
    }

    unsigned myKey = 0x80000000u | lane;
    int cnt = 0;
    for (int base = start; base < e; base += 2) {
        int p = base + sub;
        bool valid = (p < e);
        int j = valid ? g_col[p] : i;
        float4 ga = ((const float4*)(g_Fu + (size_t)j * 64))[sl];
        float d;
        d = fa.x * ga.x;
        d = fmaf(fa.y, ga.y, d);
        d = fmaf(fa.z, ga.z, d);
        d = fmaf(fa.w, ga.w, d);
        d += __shfl_xor_sync(FULLM, d, 1);
        d += __shfl_xor_sync(FULLM, d, 2);
        d += __shfl_xor_sync(FULLM, d, 4);
        d += __shfl_xor_sync(FULLM, d, 8);
        float y = fminf(fmaxf(1.0f - d, 0.0f), 2.0f);
        if (valid && sl == 0) {
            g_y[p] = y;               // lanes 0 and 16 store
            g_y[g_tr[p]] = y;         // mirror entry (exact same value)
        }
        float y0 = __shfl_sync(FULLM, y, 0);
        float y1 = __shfl_sync(FULLM, y, 16);
        int nv = (e - base >= 2) ? 2 : 1;
        if (lane == cnt)                 myKey = __float_as_uint(y0) >> 16;
        if (lane == cnt + 1 && nv == 2)  myKey = __float_as_uint(y1) >> 16;
        cnt += nv;
        if (cnt == 32) {
            unsigned grp = __match_any_sync(FULLM, myKey);
            if (!(myKey & 0x80000000u)) {
                int leader = __ffs(grp) - 1;
                if (lane == leader) atomicAdd(&g_hist1[myKey], 2u * (unsigned)__popc(grp));
            }
            myKey = 0x80000000u | lane;
            cnt = 0;
        }
    }
    if (cnt) {
        unsigned grp = __match_any_sync(FULLM, myKey);
        if (!(myKey & 0x80000000u)) {
            int leader = __ffs(grp) - 1;
            if (lane == leader) atomicAdd(&g_hist1[myKey], 2u * (unsigned)__popc(grp));
        }
    }
}

// ------------------------- pass 1a: chunk sums (64 blocks) -------------------
__global__ void k_chunks() {
    __shared__ unsigned sred[8];
    int tid = threadIdx.x;      // 256
    int base = blockIdx.x * 1024;
    unsigned s = 0;
#pragma unroll
    for (int q = 0; q < 4; q++) s += g_hist1[base + q * 256 + tid];
#pragma unroll
    for (int o = 16; o; o >>= 1) s += __shfl_xor_sync(FULLM, s, o);
    if ((tid & 31) == 0) sred[tid >> 5] = s;
    __syncthreads();
    if (tid < 8) {
        unsigned v = sred[tid];
#pragma unroll
        for (int o = 4; o; o >>= 1) v += __shfl_xor_sync(0xffu, v, o);
        if (tid == 0) g_chunk[blockIdx.x] = v;
    }
}

// ------------------------- pass 1b: pick buckets (1 block, 256 thr) ----------
__global__ void k_pick() {
    __shared__ int sW0, sR0, sW1, sR1;
    int tid = threadIdx.x;
    int m = g_nnz;
    if (m <= 0) {
        if (tid == 0) { g_b0 = 0; g_b1 = 0; g_rem0 = 0; g_rem1 = 0; g_c0 = 0; g_c1 = 0; }
        return;
    }
    long p3 = 3L * (long)(m - 1);
    int k0 = (int)(p3 >> 2);
    int k1 = (k0 + 1 < m) ? k0 + 1 : m - 1;
    if (tid == 0) {
        unsigned run = 0;
        for (int q = 0; q < NCHUNK; q++) {
            unsigned c = g_chunk[q];
            if ((unsigned)k0 >= run && (unsigned)k0 < run + c) { sW0 = q; sR0 = (int)((unsigned)k0 - run); }
            if ((unsigned)k1 >= run && (unsigned)k1 < run + c) { sW1 = q; sR1 = (int)((unsigned)k1 - run); }
            run += c;
        }
        g_c0 = 0; g_c1 = 0;
    }
    __syncthreads();
    for (int sel = 0; sel < 2; sel++) {
        int w = sel ? sW1 : sW0;
        unsigned rank = (unsigned)(sel ? sR1 : sR0);
        __shared__ unsigned h[1024];
        int base = w * 1024;
#pragma unroll
        for (int q = 0; q < 4; q++) h[q * 256 + tid] = g_hist1[base + q * 256 + tid];
        __syncthreads();
        __shared__ unsigned tsum[256];
        unsigned v0 = h[tid * 4], v1 = h[tid * 4 + 1], v2 = h[tid * 4 + 2], v3 = h[tid * 4 + 3];
        unsigned loc = v0 + v1 + v2 + v3;
        tsum[tid] = loc;
        __syncthreads();
        for (int off = 1; off < 256; off <<= 1) {
            unsigned x = (tid >= off) ? tsum[tid - off] : 0u;
            __syncthreads();
            tsum[tid] += x;
            __syncthreads();
        }
        unsigned exc = tsum[tid] - loc;
        unsigned r0 = exc, r1 = exc + v0, r2 = r1 + v1, r3 = r2 + v2, r4 = r3 + v3;
        if (rank >= r0 && rank < r4) {
            int b; unsigned pr;
            if (rank < r1)      { b = 0; pr = r0; }
            else if (rank < r2) { b = 1; pr = r1; }
            else if (rank < r3) { b = 2; pr = r2; }
            else                { b = 3; pr = r3; }
            if (sel == 0) { g_b0 = (unsigned)(base + tid * 4 + b); g_rem0 = (int)(rank - pr); }
            else          { g_b1 = (unsigned)(base + tid * 4 + b); g_rem1 = (int)(rank - pr); }
        }
        __syncthreads();
    }
}

// ------------------------- pass 2: collect candidates (+zero hist1) ----------
__global__ void k_qrefine() {
    int m = g_nnz;
    unsigned b0 = g_b0, b1 = g_b1;
    bool same = (b1 == b0);
    int gid = blockIdx.x * blockDim.x + threadIdx.x;
    int stride = gridDim.x * blockDim.x;
    for (int z = gid; z < 65536; z += stride) g_hist1[z] = 0u;
    for (int e = gid; e < m; e += stride) {
        unsigned bits = __float_as_uint(g_y[e]);
        unsigned hi = bits >> 16;
        if (hi == b0) {
            int idx = atomicAdd(&g_c0, 1);
            g_buf0[idx] = (unsigned short)(bits & 0xFFFFu);
        } else if (!same && hi == b1) {
            int idx = atomicAdd(&g_c1, 1);
            g_buf1[idx] = (unsigned short)(bits & 0xFFFFu);
        }
    }
}

// ------------------------- smem 8/8 radix select within a bucket -------------
__device__ void select16(const unsigned short* __restrict__ buf, int cnt, int rank,
                         unsigned* out /* shared */) {
    __shared__ unsigned h[256];
    __shared__ int sHB, sRem;
    int tid = threadIdx.x;
    h[tid] = 0u;
    __syncthreads();
    for (int i = tid; i < cnt; i += 256) atomicAdd(&h[buf[i] >> 8], 1u);
    __syncthreads();
    unsigned v = h[tid];
    for (int off = 1; off < 256; off <<= 1) {
        unsigned x = (tid >= off) ? h[tid - off] : 0u;
        __syncthreads();
        h[tid] += x;
        __syncthreads();
    }
    unsigned inc = h[tid], exc = inc - v;
    if ((unsigned)rank >= exc && (unsigned)rank < inc) { sHB = tid; sRem = (int)((unsigned)rank - exc); }
    __syncthreads();
    int hb = sHB, rem = sRem;
    h[tid] = 0u;
    __syncthreads();
    for (int i = tid; i < cnt; i += 256) {
        unsigned b = buf[i];
        if ((int)(b >> 8) == hb) atomicAdd(&h[b & 0xFFu], 1u);
    }
    __syncthreads();
    v = h[tid];
    for (int off = 1; off < 256; off <<= 1) {
        unsigned x = (tid >= off) ? h[tid - off] : 0u;
        __syncthreads();
        h[tid] += x;
        __syncthreads();
    }
    inc = h[tid]; exc = inc - v;
    if ((unsigned)rem >= exc && (unsigned)rem < inc) *out = ((unsigned)hb << 8) | (unsigned)tid;
    __syncthreads();
}

// ------------------------- finalize: select + lamc (1 block) -----------------
__global__ void k_qfinal(const float* __restrict__ lg0p, const float* __restrict__ rdp,
                         const float* __restrict__ rabp, int kiter) {
    __shared__ unsigned sLow[2];
    int m = g_nnz;
    unsigned b0 = g_b0, b1 = g_b1;
    bool same = (b1 == b0);
    if (m > 0) {
        int c0 = g_c0, c1 = g_c1;
        select16(g_buf0, c0, g_rem0, &sLow[0]);
        if (same) select16(g_buf0, c0, g_rem1, &sLow[1]);
        else      select16(g_buf1, c1, g_rem1, &sLow[1]);
    }
    if (threadIdx.x == 0) {
        float gd;
        if (m > 0) {
            float v0 = __uint_as_float((b0 << 16) | sLow[0]);
            float v1 = __uint_as_float((b1 << 16) | sLow[1]);
            long p3 = 3L * (long)(m - 1);
            float frac = (float)(p3 & 3) * 0.25f;
            gd = v0 + (v1 - v0) * frac;
        } else {
            gd = 1.0f;
        }
        gd = fmaxf(gd, EPS_F);
        float alpha = sigmoidf_(*rabp);
        float r = sigmoidf_(*rdp);
        float gp = expf(*lg0p);
        for (int q = 0; q < kiter; q++) gp *= r;
        g_lamc = alpha * (gp / A_SCAD) + (1.0f - alpha) * (gd / A_SCAD);
    }
}

// ------------------------- SpMM + Q_hat + update (+fused Fu) -----------------
__global__ void k_spmm(int src, int dst, float* __restrict__ dout, int N, int OUT,
                       int writeFu) {
    int i = blockIdx.x;
    int t = threadIdx.x;   // 64
    const float* __restrict__ Fc = (src == 0) ? g_F0 : (src == 1) ? g_FcA : g_FcB;
    float* __restrict__ Fout = (dst == 1) ? g_FcA : (dst == 2) ? g_FcB : dout;
    __shared__ float s_wsc[64];
    __shared__ int   s_col[64];
    __shared__ float s_q[2];
    __shared__ float s_n[2];
    float lamc = g_lamc;
    int s = g_rowptr[i], e = g_rowptr[i + 1];
    float acc = 0.0f, qpart = 0.0f;
    for (int base = s; base < e; base += 64) {
        int p = base + t;
        float wc = 0.0f; int col = 0;
        if (p < e) {
            float y = g_y[p];
            float wgt = scad_w(y, lamc);
            col = g_col[p];
            wc = wgt * g_invDsq[col];
            qpart += wgt;
        }
        s_wsc[t] = wc; s_col[t] = col;
        __syncthreads();
        int len = e - base; if (len > 64) len = 64;
        if (t < OUT) {
#pragma unroll 4
            for (int q = 0; q < len; q++)
                acc = fmaf(s_wsc[q], Fc[(size_t)s_col[q] * OUT + t], acc);
        }
        __syncthreads();
    }
#pragma unroll
    for (int o = 16; o; o >>= 1) qpart += __shfl_xor_sync(FULLM, qpart, o);
    if ((t & 31) == 0) s_q[t >> 5] = qpart;
    __syncthreads();
    float val = 0.0f;
    float iq = g_invDsq[i];
    if (t < OUT) {
        float Qh = (s_q[0] + s_q[1]) / g_D[i] + LAM_CONST;
        val = (acc * iq + LAM_CONST * g_F0[(size_t)i * OUT + t]) / Qh;
        Fout[(size_t)i * OUT + t] = val;
    }
    if (writeFu) {
        float fn = (t < OUT) ? val * iq : 0.0f;
        float ss = fn * fn;
#pragma unroll
        for (int o = 16; o; o >>= 1) ss += __shfl_xor_sync(FULLM, ss, o);
        if ((t & 31) == 0) s_n[t >> 5] = ss;
        __syncthreads();
        float nrm = sqrtf(s_n[0] + s_n[1]);
        float d = fmaxf(nrm, EPS_F);
        if (t < OUT) g_Fu[(size_t)i * OUT + t] = fn / d;
    }
}

// ------------------------- launch -------------------------
extern "C" void kernel_launch(void* const* d_in, const int* in_sizes, int n_in,
                              void* d_out, int out_size) {
    const float* A   = (const float*)d_in[0];
    const float* X   = (const float*)d_in[1];
    const float* W1  = (const float*)d_in[2];
    const float* b1  = (const float*)d_in[3];
    const float* W2  = (const float*)d_in[4];
    const float* b2  = (const float*)d_in[5];
    const float* lg0 = (const float*)d_in[6];
    const float* rd  = (const float*)d_in[7];
    const float* rab = (const float*)d_in[8];
    float* out = (float*)d_out;

    int H   = in_sizes[3];
    int OUT = in_sizes[5];
    int IN  = in_sizes[2] / H;
    int N   = in_sizes[1] / IN;

    int warpBlocks = (N * 32 + 255) / 256;

    // graph structure (rowstats zeroes hist1 for iter 0)
    k_rowstats<<<warpBlocks, 256>>>(A, N);
    k_scan<<<1, 1024>>>(N);
    k_fill<<<warpBlocks, 256>>>(N);
    k_transpose<<<warpBlocks, 256>>>(N);

    // MLP: F0 = relu(X@W1 + b1) @ W2 + b2 ; gemm2 fuses Fu epilogue
    float* H1p;  cudaGetSymbolAddress((void**)&H1p, g_H1);
    dim3 g1(H / 64, N / 64);
    k_gemm1<<<g1, 256>>>(X, W1, b1, H1p, N, IN, H);
    dim3 g2(1, N / 64);
    k_gemm2fu<<<g2, 256>>>(W2, b2, N, H, OUT);

    // propagation: F0 -> FcA -> FcB -> FcA -> d_out
    const int srcs[4] = {0, 1, 2, 1};
    const int dsts[4] = {1, 2, 1, 3};
    for (int k = 0; k < 4; k++) {
        k_edge_y<<<warpBlocks, 256>>>(N);
        k_chunks<<<NCHUNK, 256>>>();
        k_pick<<<1, 256>>>();
        k_qrefine<<<296, 256>>>();
        k_qfinal<<<1, 256>>>(lg0, rd, rab, k);
        k_spmm<<<N, 64>>>(srcs[k], dsts[k], out, N, OUT, (k < 3) ? 1 : 0);
    }
}